// round 1
// baseline (speedup 1.0000x reference)
#include <cuda_runtime.h>
#include <math.h>

#define BATCH 16384
#define SEQ   50
#define DIM   300
#define HID   32
#define OUTC  2

// scratch for column-wise logsumexp (allocation-free: __device__ global)
__device__ float g_lse[2];

// ---------------------------------------------------------------------------
// Kernel 1: gather + mean-pool + 2-layer MLP head -> logits into d_out
// One CTA per batch row. 320 threads (300 active for the gather).
// ---------------------------------------------------------------------------
__global__ __launch_bounds__(320) void dan_main(
    const int*   __restrict__ tokens,
    const float* __restrict__ emb,
    const float* __restrict__ Vw,
    const float* __restrict__ Vb,
    const float* __restrict__ Ww,
    const float* __restrict__ Wb,
    float*       __restrict__ out)
{
    __shared__ int   sTok[SEQ];
    __shared__ float sPooled[DIM];
    __shared__ float sH[HID];

    const int tid = threadIdx.x;
    const int b   = blockIdx.x;

    if (tid < SEQ) sTok[tid] = tokens[b * SEQ + tid];
    __syncthreads();

    // ---- gather + mean pool: thread d accumulates emb[tok_k][d] over k ----
    if (tid < DIM) {
        float acc = 0.f;
        #pragma unroll 10
        for (int k = 0; k < SEQ; k++) {
            // row base = tok*300 floats; warp reads 32 consecutive floats
            acc += __ldg(emb + (size_t)sTok[k] * DIM + tid);
        }
        sPooled[tid] = acc * (1.0f / (float)SEQ);
    }
    __syncthreads();

    // ---- h = relu(pooled @ Vw^T + Vb): per-warp coalesced dot products ----
    const int w    = tid >> 5;
    const int lane = tid & 31;
    for (int j = w; j < HID; j += 10) {          // 10 warps cover 32 outputs
        float p = 0.f;
        for (int d = lane; d < DIM; d += 32)     // coalesced Vw row read
            p += sPooled[d] * Vw[j * DIM + d];
        #pragma unroll
        for (int off = 16; off; off >>= 1)
            p += __shfl_down_sync(0xffffffffu, p, off);
        if (lane == 0) sH[j] = fmaxf(p + Vb[j], 0.f);
    }
    __syncthreads();

    // ---- logits = h @ Ww^T + Wb (2 outputs) ----
    if (tid < OUTC) {
        float acc = Wb[tid];
        #pragma unroll
        for (int j = 0; j < HID; j++)
            acc += sH[j] * Ww[tid * HID + j];
        out[b * OUTC + tid] = acc;
    }
}

// ---------------------------------------------------------------------------
// Kernel 2: column-wise logsumexp over the batch axis (axis=0), single CTA.
// ---------------------------------------------------------------------------
__global__ __launch_bounds__(1024) void lse_kernel(const float* __restrict__ logits)
{
    __shared__ float2 red[1024];
    const int tid = threadIdx.x;

    float m0 = -1e30f, m1 = -1e30f;
    for (int r = tid; r < BATCH; r += 1024) {
        float2 v = reinterpret_cast<const float2*>(logits)[r];
        m0 = fmaxf(m0, v.x);
        m1 = fmaxf(m1, v.y);
    }
    red[tid] = make_float2(m0, m1);
    __syncthreads();
    for (int s = 512; s; s >>= 1) {
        if (tid < s) {
            red[tid].x = fmaxf(red[tid].x, red[tid + s].x);
            red[tid].y = fmaxf(red[tid].y, red[tid + s].y);
        }
        __syncthreads();
    }
    m0 = red[0].x;
    m1 = red[0].y;
    __syncthreads();

    float s0 = 0.f, s1 = 0.f;
    for (int r = tid; r < BATCH; r += 1024) {
        float2 v = reinterpret_cast<const float2*>(logits)[r];
        s0 += expf(v.x - m0);
        s1 += expf(v.y - m1);
    }
    red[tid] = make_float2(s0, s1);
    __syncthreads();
    for (int s = 512; s; s >>= 1) {
        if (tid < s) {
            red[tid].x += red[tid + s].x;
            red[tid].y += red[tid + s].y;
        }
        __syncthreads();
    }
    if (tid == 0) {
        g_lse[0] = m0 + logf(red[0].x);
        g_lse[1] = m1 + logf(red[0].y);
    }
}

// ---------------------------------------------------------------------------
// Kernel 3: apply log_softmax in place: out[b,c] = logits[b,c] - lse[c]
// ---------------------------------------------------------------------------
__global__ void apply_kernel(float* __restrict__ out)
{
    const int i = blockIdx.x * blockDim.x + threadIdx.x;
    if (i < BATCH * OUTC) out[i] -= g_lse[i & 1];
}

extern "C" void kernel_launch(void* const* d_in, const int* in_sizes, int n_in,
                              void* d_out, int out_size)
{
    const int*   tokens = (const int*)  d_in[0];
    const float* emb    = (const float*)d_in[1];
    const float* Vw     = (const float*)d_in[2];
    const float* Vb     = (const float*)d_in[3];
    const float* Ww     = (const float*)d_in[4];
    const float* Wb     = (const float*)d_in[5];
    float* out = (float*)d_out;

    dan_main<<<BATCH, 320>>>(tokens, emb, Vw, Vb, Ww, Wb, out);
    lse_kernel<<<1, 1024>>>(out);
    apply_kernel<<<(BATCH * OUTC + 255) / 256, 256>>>(out);
}

// round 2
// speedup vs baseline: 1.3048x; 1.3048x over previous
#include <cuda_runtime.h>
#include <math.h>
#include <stdint.h>

#define BATCH 16384
#define SEQ   50
#define DIM   300
#define HID   32
#define OUTC  2
#define VOCAB 400000

// allocation-free scratch
__device__ float g_lse[2];
__device__ float g_E2[(size_t)VOCAB * HID];   // 51.2 MB projected table

// ---------------------------------------------------------------------------
// Pass A: E2[v][j] = sum_d emb[v][d] * Vw[j][d]   (400000x300 @ 300x32)
// tf32 mma.sync m16n8k8. Persistent CTAs, 128 threads, 32-row tiles in smem.
// A smem stride 308 floats -> LDS fragment reads are bank-conflict-free.
// ---------------------------------------------------------------------------
#define TILE_R   32
#define KSTEPS   38          // ceil(300/8)
#define A_STRIDE 308         // 300 + 8 zero-pad
#define NTILES   4           // 32 cols / 8
#define NT_TILES (VOCAB / TILE_R)   // 12500
#define A_ELEMS  (TILE_R * A_STRIDE)
#define B_ELEMS  (KSTEPS * NTILES * 2 * 32)   // 9728
#define SMEM_BYTES ((A_ELEMS + B_ELEMS) * 4)  // 78336

__global__ __launch_bounds__(128) void project_kernel(
    const float* __restrict__ emb,
    const float* __restrict__ Vw)
{
    extern __shared__ float smem[];
    float*    sA = smem;                       // [32][308]
    uint32_t* sB = (uint32_t*)(smem + A_ELEMS); // tf32 B fragments

    const int tid  = threadIdx.x;
    const int warp = tid >> 5;
    const int lane = tid & 31;
    const int g4   = lane >> 2;   // groupID
    const int tg   = lane & 3;    // thread-in-group

    // fill B fragments once (pre-converted to tf32), zero-padded past k=299
    for (int i = tid; i < B_ELEMS; i += 128) {
        int l  = i & 31;
        int h  = (i >> 5) & 1;
        int nt = (i >> 6) & 3;
        int ks = i >> 8;
        int k  = ks * 8 + h * 4 + (l & 3);
        int n  = nt * 8 + (l >> 2);
        float v = (k < DIM) ? Vw[n * DIM + k] : 0.0f;
        uint32_t b;
        asm("cvt.rna.tf32.f32 %0, %1;" : "=r"(b) : "f"(v));
        sB[i] = b;
    }
    // zero the 8 pad columns of each A row (never overwritten afterwards)
    for (int i = tid; i < TILE_R * 8; i += 128) {
        int r = i >> 3;
        sA[r * A_STRIDE + DIM + (i & 7)] = 0.0f;
    }
    __syncthreads();

    const int rowHalf = warp >> 1;                   // 0/1 -> rows 0-15 / 16-31
    const int colHalf = warp & 1;                    // 0/1 -> cols 0-15 / 16-31
    const int aRow    = rowHalf * 16 + g4;

    for (int t = blockIdx.x; t < NT_TILES; t += gridDim.x) {
        // --- async copy 32x300 fp32 tile (contiguous 38400B in global) ---
        const float4* src = (const float4*)(emb + (size_t)t * TILE_R * DIM);
        for (int i = tid; i < TILE_R * DIM / 4; i += 128) {
            int r = i / 75;                  // 75 float4 per row
            int c = i - r * 75;
            uint32_t dst = (uint32_t)__cvta_generic_to_shared(&sA[r * A_STRIDE + c * 4]);
            asm volatile("cp.async.cg.shared.global [%0], [%1], 16;\n"
                         :: "r"(dst), "l"(src + i));
        }
        asm volatile("cp.async.commit_group;\ncp.async.wait_group 0;\n");
        __syncthreads();

        float c0[2] = {0.f, 0.f}, c1[2] = {0.f, 0.f};
        float c2[2] = {0.f, 0.f}, c3[2] = {0.f, 0.f};

        #pragma unroll 2
        for (int ks = 0; ks < KSTEPS; ks++) {
            const float* ap = &sA[aRow * A_STRIDE + ks * 8 + tg];
            float a0f = ap[0];
            float a1f = ap[8 * A_STRIDE];
            float a2f = ap[4];
            float a3f = ap[8 * A_STRIDE + 4];
            uint32_t a0, a1, a2, a3;
            asm("cvt.rna.tf32.f32 %0, %1;" : "=r"(a0) : "f"(a0f));
            asm("cvt.rna.tf32.f32 %0, %1;" : "=r"(a1) : "f"(a1f));
            asm("cvt.rna.tf32.f32 %0, %1;" : "=r"(a2) : "f"(a2f));
            asm("cvt.rna.tf32.f32 %0, %1;" : "=r"(a3) : "f"(a3f));

            #pragma unroll
            for (int s = 0; s < 2; s++) {
                int nt = colHalf * 2 + s;
                uint32_t b0 = sB[((ks * 4 + nt) * 2 + 0) * 32 + lane];
                uint32_t b1 = sB[((ks * 4 + nt) * 2 + 1) * 32 + lane];
                asm volatile(
                    "mma.sync.aligned.m16n8k8.row.col.f32.tf32.tf32.f32 "
                    "{%0,%1,%2,%3}, {%4,%5,%6,%7}, {%8,%9}, {%0,%1,%2,%3};\n"
                    : "+f"(c0[s]), "+f"(c1[s]), "+f"(c2[s]), "+f"(c3[s])
                    : "r"(a0), "r"(a1), "r"(a2), "r"(a3), "r"(b0), "r"(b1));
            }
        }
        __syncthreads();   // protect sA before next tile's copy

        // --- store 16x8 C fragments (float2 stores) ---
        int rbase = t * TILE_R + rowHalf * 16;
        #pragma unroll
        for (int s = 0; s < 2; s++) {
            int col = colHalf * 16 + s * 8 + tg * 2;
            int r0  = rbase + g4;
            *(float2*)&g_E2[(size_t)r0 * HID + col]       = make_float2(c0[s], c1[s]);
            *(float2*)&g_E2[(size_t)(r0 + 8) * HID + col] = make_float2(c2[s], c3[s]);
        }
    }
}

// ---------------------------------------------------------------------------
// Pass B: gather E2 rows, mean-pool, relu MLP head -> logits.
// One warp per batch row; lane = hidden unit. 128B coalesced gathers.
// ---------------------------------------------------------------------------
__global__ __launch_bounds__(256) void gather_kernel(
    const int*   __restrict__ tokens,
    const float* __restrict__ Vb,
    const float* __restrict__ Ww,
    const float* __restrict__ Wb,
    float*       __restrict__ out)
{
    const int b    = blockIdx.x * 8 + (threadIdx.x >> 5);
    const int lane = threadIdx.x & 31;

    int t0 = tokens[b * SEQ + lane];
    int t1 = (lane < SEQ - 32) ? tokens[b * SEQ + 32 + lane] : 0;

    float acc = 0.f;
    #pragma unroll
    for (int k = 0; k < SEQ; k++) {
        int tok = (k < 32) ? __shfl_sync(0xffffffffu, t0, k)
                           : __shfl_sync(0xffffffffu, t1, k - 32);
        acc += __ldg(&g_E2[(size_t)tok * HID + lane]);
    }

    float h  = fmaxf(acc * (1.0f / (float)SEQ) + Vb[lane], 0.f);
    float p0 = h * Ww[lane];          // Ww[0][lane]
    float p1 = h * Ww[HID + lane];    // Ww[1][lane]
    #pragma unroll
    for (int off = 16; off; off >>= 1) {
        p0 += __shfl_xor_sync(0xffffffffu, p0, off);
        p1 += __shfl_xor_sync(0xffffffffu, p1, off);
    }
    if (lane == 0) {
        out[b * OUTC + 0] = p0 + Wb[0];
        out[b * OUTC + 1] = p1 + Wb[1];
    }
}

// ---------------------------------------------------------------------------
// Pass C: column-wise logsumexp over the batch axis, single CTA.
// ---------------------------------------------------------------------------
__global__ __launch_bounds__(1024) void lse_kernel(const float* __restrict__ logits)
{
    __shared__ float2 red[1024];
    const int tid = threadIdx.x;

    float m0 = -1e30f, m1 = -1e30f;
    for (int r = tid; r < BATCH; r += 1024) {
        float2 v = reinterpret_cast<const float2*>(logits)[r];
        m0 = fmaxf(m0, v.x);
        m1 = fmaxf(m1, v.y);
    }
    red[tid] = make_float2(m0, m1);
    __syncthreads();
    for (int s = 512; s; s >>= 1) {
        if (tid < s) {
            red[tid].x = fmaxf(red[tid].x, red[tid + s].x);
            red[tid].y = fmaxf(red[tid].y, red[tid + s].y);
        }
        __syncthreads();
    }
    m0 = red[0].x; m1 = red[0].y;
    __syncthreads();

    float s0 = 0.f, s1 = 0.f;
    for (int r = tid; r < BATCH; r += 1024) {
        float2 v = reinterpret_cast<const float2*>(logits)[r];
        s0 += expf(v.x - m0);
        s1 += expf(v.y - m1);
    }
    red[tid] = make_float2(s0, s1);
    __syncthreads();
    for (int s = 512; s; s >>= 1) {
        if (tid < s) {
            red[tid].x += red[tid + s].x;
            red[tid].y += red[tid + s].y;
        }
        __syncthreads();
    }
    if (tid == 0) {
        g_lse[0] = m0 + logf(red[0].x);
        g_lse[1] = m1 + logf(red[0].y);
    }
}

__global__ void apply_kernel(float* __restrict__ out)
{
    const int i = blockIdx.x * blockDim.x + threadIdx.x;
    if (i < BATCH * OUTC) out[i] -= g_lse[i & 1];
}

extern "C" void kernel_launch(void* const* d_in, const int* in_sizes, int n_in,
                              void* d_out, int out_size)
{
    const int*   tokens = (const int*)  d_in[0];
    const float* emb    = (const float*)d_in[1];
    const float* Vw     = (const float*)d_in[2];
    const float* Vb     = (const float*)d_in[3];
    const float* Ww     = (const float*)d_in[4];
    const float* Wb     = (const float*)d_in[5];
    float* out = (float*)d_out;

    cudaFuncSetAttribute(project_kernel,
                         cudaFuncAttributeMaxDynamicSharedMemorySize, SMEM_BYTES);

    project_kernel<<<296, 128, SMEM_BYTES>>>(emb, Vw);
    gather_kernel<<<BATCH / 8, 256>>>(tokens, Vb, Ww, Wb, out);
    lse_kernel<<<1, 1024>>>(out);
    apply_kernel<<<(BATCH * OUTC + 255) / 256, 256>>>(out);
}

// round 3
// speedup vs baseline: 1.5919x; 1.2201x over previous
#include <cuda_runtime.h>
#include <math.h>
#include <stdint.h>

#define BATCH 16384
#define SEQ   50
#define DIM   300
#define HID   32
#define OUTC  2
#define VOCAB 400000

// allocation-free scratch
__device__ float g_lse[2];
__device__ float g_E2[(size_t)VOCAB * HID];   // 51.2 MB projected table

// ---------------------------------------------------------------------------
// Pass A: E2[v][j] = sum_d emb[v][d] * Vw[j][d]   (400000x300 @ 300x32)
// tf32 mma.sync m16n8k8. Persistent CTAs (148), 256 threads, 64-row tiles,
// 2-stage cp.async double buffering. A smem stride 308 -> conflict-free LDS.
// ---------------------------------------------------------------------------
#define TILE_R   64
#define KSTEPS   38                         // ceil(300/8)
#define A_STRIDE 308                        // 300 + 8 zero-pad
#define NT_TILES (VOCAB / TILE_R)           // 6250
#define A_ELEMS  (TILE_R * A_STRIDE)        // 19712 floats / stage
#define B_ELEMS  (KSTEPS * 4 * 2 * 32)      // 9728 floats
#define SMEM_BYTES ((2 * A_ELEMS + B_ELEMS) * 4)   // 196608 B

__device__ __forceinline__ void prefetch_tile(
    const float* __restrict__ emb, float* __restrict__ sA, int t, int tid)
{
    const float4* src = (const float4*)(emb + (size_t)t * TILE_R * DIM);
    #pragma unroll
    for (int it = 0; it < (TILE_R * DIM / 4 + 255) / 256; it++) {
        int i = it * 256 + tid;
        if (i < TILE_R * DIM / 4) {
            int r = i / 75;                  // 75 float4 per row
            int c = i - r * 75;
            uint32_t dst = (uint32_t)__cvta_generic_to_shared(&sA[r * A_STRIDE + c * 4]);
            asm volatile("cp.async.cg.shared.global [%0], [%1], 16;\n"
                         :: "r"(dst), "l"(src + i));
        }
    }
}

__global__ __launch_bounds__(256) void project_kernel(
    const float* __restrict__ emb,
    const float* __restrict__ Vw)
{
    extern __shared__ float smem[];
    float*    sA0 = smem;                         // stage 0: [64][308]
    float*    sA1 = smem + A_ELEMS;               // stage 1
    uint32_t* sB  = (uint32_t*)(smem + 2 * A_ELEMS);

    const int tid  = threadIdx.x;
    const int warp = tid >> 5;
    const int lane = tid & 31;
    const int g4   = lane >> 2;
    const int tg   = lane & 3;

    // kick off first tile load ASAP
    int t = blockIdx.x;
    if (t < NT_TILES) prefetch_tile(emb, sA0, t, tid);
    asm volatile("cp.async.commit_group;\n");

    // fill B fragments once (pre-converted to tf32), zero-padded past k=299
    for (int i = tid; i < B_ELEMS; i += 256) {
        int l  = i & 31;
        int h  = (i >> 5) & 1;
        int nt = (i >> 6) & 3;
        int ks = i >> 8;
        int k  = ks * 8 + h * 4 + (l & 3);
        int n  = nt * 8 + (l >> 2);
        float v = (k < DIM) ? Vw[n * DIM + k] : 0.0f;
        uint32_t b;
        asm("cvt.rna.tf32.f32 %0, %1;" : "=r"(b) : "f"(v));
        sB[i] = b;
    }
    // zero the 8 pad columns of every A row in BOTH stages (written once)
    for (int i = tid; i < TILE_R * 8; i += 256) {
        int r = i >> 3, c = i & 7;
        sA0[r * A_STRIDE + DIM + c] = 0.0f;
        sA1[r * A_STRIDE + DIM + c] = 0.0f;
    }

    const int warpRow = warp >> 1;                // 0..3 -> rows 16*warpRow
    const int colHalf = warp & 1;                 // 0/1 -> cols 0-15 / 16-31
    const int aRow    = warpRow * 16 + g4;

    int stage = 0;
    for (; t < NT_TILES; t += gridDim.x) {
        int  tn      = t + gridDim.x;
        bool hasNext = tn < NT_TILES;
        if (hasNext) prefetch_tile(emb, stage ? sA0 : sA1, tn, tid);
        asm volatile("cp.async.commit_group;\n");   // (possibly empty) group
        asm volatile("cp.async.wait_group 1;\n");   // tile t's data is in
        __syncthreads();

        const float* sA = stage ? sA1 : sA0;

        float c0[2] = {0.f, 0.f}, c1[2] = {0.f, 0.f};
        float c2[2] = {0.f, 0.f}, c3[2] = {0.f, 0.f};

        #pragma unroll 2
        for (int ks = 0; ks < KSTEPS; ks++) {
            const float* ap = &sA[aRow * A_STRIDE + ks * 8 + tg];
            float a0f = ap[0];
            float a1f = ap[8 * A_STRIDE];
            float a2f = ap[4];
            float a3f = ap[8 * A_STRIDE + 4];
            uint32_t a0, a1, a2, a3;
            asm("cvt.rna.tf32.f32 %0, %1;" : "=r"(a0) : "f"(a0f));
            asm("cvt.rna.tf32.f32 %0, %1;" : "=r"(a1) : "f"(a1f));
            asm("cvt.rna.tf32.f32 %0, %1;" : "=r"(a2) : "f"(a2f));
            asm("cvt.rna.tf32.f32 %0, %1;" : "=r"(a3) : "f"(a3f));

            #pragma unroll
            for (int s = 0; s < 2; s++) {
                int nt = colHalf * 2 + s;
                uint32_t b0 = sB[((ks * 4 + nt) * 2 + 0) * 32 + lane];
                uint32_t b1 = sB[((ks * 4 + nt) * 2 + 1) * 32 + lane];
                asm volatile(
                    "mma.sync.aligned.m16n8k8.row.col.f32.tf32.tf32.f32 "
                    "{%0,%1,%2,%3}, {%4,%5,%6,%7}, {%8,%9}, {%0,%1,%2,%3};\n"
                    : "+f"(c0[s]), "+f"(c1[s]), "+f"(c2[s]), "+f"(c3[s])
                    : "r"(a0), "r"(a1), "r"(a2), "r"(a3), "r"(b0), "r"(b1));
            }
        }

        // store 16x16 per warp (float2 stores)
        int rbase = t * TILE_R + warpRow * 16;
        #pragma unroll
        for (int s = 0; s < 2; s++) {
            int col = colHalf * 16 + s * 8 + tg * 2;
            int r0  = rbase + g4;
            *(float2*)&g_E2[(size_t)r0 * HID + col]       = make_float2(c0[s], c1[s]);
            *(float2*)&g_E2[(size_t)(r0 + 8) * HID + col] = make_float2(c2[s], c3[s]);
        }

        __syncthreads();   // all warps done reading this stage before refill
        stage ^= 1;
    }
}

// ---------------------------------------------------------------------------
// Pass B: gather E2 rows, mean-pool, relu MLP head -> logits.
// One warp per batch row; lane = hidden unit. 128B coalesced gathers.
// ---------------------------------------------------------------------------
__global__ __launch_bounds__(256) void gather_kernel(
    const int*   __restrict__ tokens,
    const float* __restrict__ Vb,
    const float* __restrict__ Ww,
    const float* __restrict__ Wb,
    float*       __restrict__ out)
{
    const int b    = blockIdx.x * 8 + (threadIdx.x >> 5);
    const int lane = threadIdx.x & 31;

    int t0 = tokens[b * SEQ + lane];
    int t1 = (lane < SEQ - 32) ? tokens[b * SEQ + 32 + lane] : 0;

    float acc = 0.f;
    #pragma unroll
    for (int k = 0; k < SEQ; k++) {
        int tok = (k < 32) ? __shfl_sync(0xffffffffu, t0, k)
                           : __shfl_sync(0xffffffffu, t1, k - 32);
        acc += __ldg(&g_E2[(size_t)tok * HID + lane]);
    }

    float h  = fmaxf(acc * (1.0f / (float)SEQ) + Vb[lane], 0.f);
    float p0 = h * Ww[lane];          // Ww[0][lane]
    float p1 = h * Ww[HID + lane];    // Ww[1][lane]
    #pragma unroll
    for (int off = 16; off; off >>= 1) {
        p0 += __shfl_xor_sync(0xffffffffu, p0, off);
        p1 += __shfl_xor_sync(0xffffffffu, p1, off);
    }
    if (lane == 0) {
        out[b * OUTC + 0] = p0 + Wb[0];
        out[b * OUTC + 1] = p1 + Wb[1];
    }
}

// ---------------------------------------------------------------------------
// Pass C: column-wise logsumexp over the batch axis + in-place subtract.
// Single CTA (fused lse + apply).
// ---------------------------------------------------------------------------
__global__ __launch_bounds__(1024) void lse_apply_kernel(float* __restrict__ logits)
{
    __shared__ float2 red[1024];
    const int tid = threadIdx.x;

    float m0 = -1e30f, m1 = -1e30f;
    for (int r = tid; r < BATCH; r += 1024) {
        float2 v = reinterpret_cast<const float2*>(logits)[r];
        m0 = fmaxf(m0, v.x);
        m1 = fmaxf(m1, v.y);
    }
    red[tid] = make_float2(m0, m1);
    __syncthreads();
    for (int s = 512; s; s >>= 1) {
        if (tid < s) {
            red[tid].x = fmaxf(red[tid].x, red[tid + s].x);
            red[tid].y = fmaxf(red[tid].y, red[tid + s].y);
        }
        __syncthreads();
    }
    m0 = red[0].x; m1 = red[0].y;
    __syncthreads();

    float s0 = 0.f, s1 = 0.f;
    for (int r = tid; r < BATCH; r += 1024) {
        float2 v = reinterpret_cast<const float2*>(logits)[r];
        s0 += expf(v.x - m0);
        s1 += expf(v.y - m1);
    }
    red[tid] = make_float2(s0, s1);
    __syncthreads();
    for (int s = 512; s; s >>= 1) {
        if (tid < s) {
            red[tid].x += red[tid + s].x;
            red[tid].y += red[tid + s].y;
        }
        __syncthreads();
    }
    __syncthreads();
    const float l0 = m0 + logf(red[0].x);
    const float l1 = m1 + logf(red[0].y);

    for (int r = tid; r < BATCH; r += 1024) {
        float2 v = reinterpret_cast<float2*>(logits)[r];
        v.x -= l0;
        v.y -= l1;
        reinterpret_cast<float2*>(logits)[r] = v;
    }
}

extern "C" void kernel_launch(void* const* d_in, const int* in_sizes, int n_in,
                              void* d_out, int out_size)
{
    const int*   tokens = (const int*)  d_in[0];
    const float* emb    = (const float*)d_in[1];
    const float* Vw     = (const float*)d_in[2];
    const float* Vb     = (const float*)d_in[3];
    const float* Ww     = (const float*)d_in[4];
    const float* Wb     = (const float*)d_in[5];
    float* out = (float*)d_out;

    cudaFuncSetAttribute(project_kernel,
                         cudaFuncAttributeMaxDynamicSharedMemorySize, SMEM_BYTES);

    project_kernel<<<148, 256, SMEM_BYTES>>>(emb, Vw);
    gather_kernel<<<BATCH / 8, 256>>>(tokens, Vb, Ww, Wb, out);
    lse_apply_kernel<<<1, 1024>>>(out);
}